// round 15
// baseline (speedup 1.0000x reference)
#include <cuda_runtime.h>
#include <cuda_fp16.h>
#include <cstdint>

// ---------------------------------------------------------------------------
// GCN_10591389352000 : 2-layer GCN + BN(train)/ReLU + linear readout
//   N=100000 nodes, E=1600000 edges, IN=H=128, OUT=40
// R13 == R12 resubmit (R12 hit an infra container failure; diff untested):
//   - direct bucketed CSR (64 slots/node, self-counting fill) -> deg_count,
//     scan1, scan3 deleted; dinv from counts in a tiny kernel
//   - gemm1 fully independent of CSR (no dinv epilogue) -> overlaps the whole
//     fill on a side stream; agg1 applies dinv[src] per edge (layer 1 only)
//   - layer 2 keeps pre-scaled form (gemm2 epilogue scales rows by dinv)
//   - GEMMs: ldmatrix + mma.sync.m16n8k16, fp16 hi/lo 3-pass; fused BN
// ---------------------------------------------------------------------------

constexpr int NN    = 100000;
constexpr int EE    = 1600000;
constexpr int HH    = 128;
constexpr int OUTC  = 40;
constexpr int SLOTS = 64;     // bucket capacity; P(deg>=64)~2e-18 for Poisson(16)

// ------------------------- device scratch (static) -------------------------
__device__ __half g_h16a[(size_t)NN * HH];  // 25.6 MB (GEMM out, agg in)
__device__ __half g_h16b[(size_t)NN * HH];  // 25.6 MB (agg out, GEMM in)
__device__ int    g_cnt[NN];
__device__ int    g_slot[(size_t)NN * SLOTS];   // 25.6 MB bucketed adjacency
__device__ float  g_dinv[NN];
__device__ float  g_bnsum[2][2 * HH];
// weight images: transposed [N][K] fp16, hi/lo split
__device__ __align__(16) __half g_w1hi[HH * HH];
__device__ __align__(16) __half g_w1lo[HH * HH];
__device__ __align__(16) __half g_w2hi[HH * HH];
__device__ __align__(16) __half g_w2lo[HH * HH];
__device__ __align__(16) __half g_wrhi[OUTC * HH];
__device__ __align__(16) __half g_wrlo[OUTC * HH];

// ------------------------- PTX helpers -------------------------------------
__device__ __forceinline__ uint32_t smem_u32(const void* p) {
    uint32_t a;
    asm("{ .reg .u64 t; cvta.to.shared.u64 t, %1; cvt.u32.u64 %0, t; }"
        : "=r"(a) : "l"(p));
    return a;
}
__device__ __forceinline__ void ldsm4(uint32_t& r0, uint32_t& r1, uint32_t& r2,
                                      uint32_t& r3, uint32_t addr) {
    asm volatile("ldmatrix.sync.aligned.m8n8.x4.shared.b16 {%0,%1,%2,%3}, [%4];"
                 : "=r"(r0), "=r"(r1), "=r"(r2), "=r"(r3) : "r"(addr));
}
__device__ __forceinline__ void mma16816(float* c, const uint32_t* a,
                                         uint32_t b0, uint32_t b1) {
    asm volatile("mma.sync.aligned.m16n8k16.row.col.f32.f16.f16.f32 "
                 "{%0,%1,%2,%3}, {%4,%5,%6,%7}, {%8,%9}, {%0,%1,%2,%3};"
                 : "+f"(c[0]), "+f"(c[1]), "+f"(c[2]), "+f"(c[3])
                 : "r"(a[0]), "r"(a[1]), "r"(a[2]), "r"(a[3]), "r"(b0), "r"(b1));
}
__device__ __forceinline__ uint32_t h2u(__half2 v) {
    return *reinterpret_cast<uint32_t*>(&v);
}

// ------------------------- CSR build: direct bucketed fill -----------------
__global__ void fill_direct_kernel(const int4* __restrict__ src4,
                                   const int4* __restrict__ dst4) {
    for (int e = blockIdx.x * blockDim.x + threadIdx.x; e < EE / 4;
         e += gridDim.x * blockDim.x) {
        int4 d = dst4[e];
        int4 s = src4[e];
        int p;
        p = atomicAdd(&g_cnt[d.x], 1); if (p < SLOTS) g_slot[(size_t)d.x * SLOTS + p] = s.x;
        p = atomicAdd(&g_cnt[d.y], 1); if (p < SLOTS) g_slot[(size_t)d.y * SLOTS + p] = s.y;
        p = atomicAdd(&g_cnt[d.z], 1); if (p < SLOTS) g_slot[(size_t)d.z * SLOTS + p] = s.z;
        p = atomicAdd(&g_cnt[d.w], 1); if (p < SLOTS) g_slot[(size_t)d.w * SLOTS + p] = s.w;
    }
}

__global__ void dinv_kernel() {
    int i = blockIdx.x * blockDim.x + threadIdx.x;
    if (i < NN) g_dinv[i] = rsqrtf((float)g_cnt[i] + 1.0f);
}

// ------------------------- weight prep (all 3 weights, one launch) ---------
__global__ void wprep_all_kernel(const float* __restrict__ W1,
                                 const float* __restrict__ W2,
                                 const float* __restrict__ Wr) {
    constexpr int T1 = HH * HH, T2 = 2 * HH * HH, T3 = 2 * HH * HH + OUTC * HH;
    for (int i = blockIdx.x * blockDim.x + threadIdx.x; i < T3;
         i += gridDim.x * blockDim.x) {
        const float* W;
        __half *hi, *lo;
        int Ncols, idx;
        if (i < T1)      { W = W1; hi = g_w1hi; lo = g_w1lo; Ncols = HH;   idx = i; }
        else if (i < T2) { W = W2; hi = g_w2hi; lo = g_w2lo; Ncols = HH;   idx = i - T1; }
        else             { W = Wr; hi = g_wrhi; lo = g_wrlo; Ncols = OUTC; idx = i - T2; }
        int n = idx / HH, k = idx % HH;
        float w = W[k * Ncols + n];
        __half h = __float2half_rn(w);
        hi[n * HH + k] = h;
        lo[n * HH + k] = __float2half_rn(w - __half2float(h));
    }
}

// ------------------------- tensor-core GEMM --------------------------------
// C[nrows, NCOL] = act(A[nrows,128]) @ W[128, NCOL] (+ bias), CTA tile M=128.
// FUSED: BN affine (per-CTA from g_bnsum/gamma/beta) + ReLU on A load.
// SCALE: multiply output row r by g_dinv[r] before fp16 store (for agg).
template <int NCOL, bool FUSED, bool BIAS, bool HALF_OUT, bool HALF_IN, bool SCALE>
__global__ void __launch_bounds__(256, 1)
mma_gemm_kernel(const void* __restrict__ Av, const __half* __restrict__ Bhi,
                const __half* __restrict__ Blo, const float* __restrict__ bias,
                const float* __restrict__ gamma, const float* __restrict__ beta,
                int which, void* __restrict__ Cv, int nrows) {
    constexpr int SA     = 272;                 // bytes per smem row
    constexpr int OFF_AH = 0;
    constexpr int OFF_AL = 128 * SA;            // 34816
    constexpr int OFF_BH = 2 * 128 * SA;        // 69632
    constexpr int OFF_BL = OFF_BH + NCOL * SA;
    constexpr int MW = (NCOL == 128) ? 2 : 1;
    constexpr int NW = (NCOL == 128) ? 8 : 5;

    extern __shared__ char smem[];
    __shared__ float s_sc[HH], s_sh[HH];
    uint32_t sb = smem_u32(smem);
    int t = threadIdx.x, wid = t >> 5, lane = t & 31;
    int row0 = blockIdx.x * 128;

    if (FUSED) {
        if (t < HH) {
            float mean = g_bnsum[which][t] * (1.0f / NN);
            float var  = g_bnsum[which][HH + t] * (1.0f / NN) - mean * mean;
            float sc   = gamma[t] * rsqrtf(var + 1e-5f);
            s_sc[t] = sc;
            s_sh[t] = fmaf(-mean, sc, beta[t]);
        }
        __syncthreads();
    }

    int mbase, wnb;
    if (NCOL == 128) { mbase = (wid & 3) * 32; wnb = (wid >> 2) * 64; }
    else             { mbase = wid * 16;       wnb = 0; }

    // ---- B copy: gmem image [n][k] fp16 -> padded smem rows ----
    {
        const uint4* shp = reinterpret_cast<const uint4*>(Bhi);
        const uint4* slp = reinterpret_cast<const uint4*>(Blo);
        uint4* dh = reinterpret_cast<uint4*>(smem + OFF_BH);
        uint4* dl = reinterpret_cast<uint4*>(smem + OFF_BL);
        for (int i = t; i < NCOL * 16; i += 256) {
            int n = i >> 4, j = i & 15;
            dh[n * 17 + j] = shp[i];
            dl[n * 17 + j] = slp[i];
        }
    }
    // ---- A load + (affine/relu) + hi/lo split -> padded smem ----
    {
        int r = t >> 1, kh = (t & 1) * 64;
        int grow = row0 + r;
        if (grow > nrows - 1) grow = nrows - 1;
        #pragma unroll
        for (int u = 0; u < 8; u++) {
            int k = kh + u * 8;
            float v[8];
            if (HALF_IN) {
                const uint4* Ar = reinterpret_cast<const uint4*>(
                    (const __half*)Av + (size_t)grow * HH + k);
                uint4 raw = Ar[0];
                float2 f0 = __half22float2(*reinterpret_cast<__half2*>(&raw.x));
                float2 f1 = __half22float2(*reinterpret_cast<__half2*>(&raw.y));
                float2 f2 = __half22float2(*reinterpret_cast<__half2*>(&raw.z));
                float2 f3 = __half22float2(*reinterpret_cast<__half2*>(&raw.w));
                v[0] = f0.x; v[1] = f0.y; v[2] = f1.x; v[3] = f1.y;
                v[4] = f2.x; v[5] = f2.y; v[6] = f3.x; v[7] = f3.y;
            } else {
                const float4* Ar = reinterpret_cast<const float4*>(
                    (const float*)Av + (size_t)grow * HH + k);
                float4 a = Ar[0], b = Ar[1];
                v[0] = a.x; v[1] = a.y; v[2] = a.z; v[3] = a.w;
                v[4] = b.x; v[5] = b.y; v[6] = b.z; v[7] = b.w;
            }
            if (FUSED) {
                #pragma unroll
                for (int j = 0; j < 8; j++)
                    v[j] = fmaxf(fmaf(v[j], s_sc[k + j], s_sh[k + j]), 0.f);
            }
            __half hv[8];
            uint4 hh, ll;
            #pragma unroll
            for (int j = 0; j < 8; j++) hv[j] = __float2half_rn(v[j]);
            hh.x = h2u(__halves2half2(hv[0], hv[1]));
            hh.y = h2u(__halves2half2(hv[2], hv[3]));
            hh.z = h2u(__halves2half2(hv[4], hv[5]));
            hh.w = h2u(__halves2half2(hv[6], hv[7]));
            ll.x = h2u(__halves2half2(__float2half_rn(v[0] - __half2float(hv[0])),
                                      __float2half_rn(v[1] - __half2float(hv[1]))));
            ll.y = h2u(__halves2half2(__float2half_rn(v[2] - __half2float(hv[2])),
                                      __float2half_rn(v[3] - __half2float(hv[3]))));
            ll.z = h2u(__halves2half2(__float2half_rn(v[4] - __half2float(hv[4])),
                                      __float2half_rn(v[5] - __half2float(hv[5]))));
            ll.w = h2u(__halves2half2(__float2half_rn(v[6] - __half2float(hv[6])),
                                      __float2half_rn(v[7] - __half2float(hv[7]))));
            uint32_t off = (uint32_t)r * SA + (uint32_t)k * 2;
            *reinterpret_cast<uint4*>(smem + OFF_AH + off) = hh;
            *reinterpret_cast<uint4*>(smem + OFF_AL + off) = ll;
        }
    }
    __syncthreads();

    // ---- fragment address offsets (per lane) ----
    uint32_t aoff = (uint32_t)((lane & 7) + ((lane >> 3) & 1) * 8) * SA
                  + (uint32_t)(((lane >> 4) & 1) * 8) * 2;
    uint32_t bside = (lane >= 16) ? (uint32_t)OFF_BL : (uint32_t)OFF_BH;
    uint32_t boff  = (uint32_t)(lane & 7) * SA + (uint32_t)(((lane >> 3) & 1) * 8) * 2;

    float acc[MW][NW][4];
    #pragma unroll
    for (int m = 0; m < MW; m++)
        #pragma unroll
        for (int n = 0; n < NW; n++)
            #pragma unroll
            for (int c = 0; c < 4; c++) acc[m][n][c] = 0.f;

    #pragma unroll
    for (int s = 0; s < 8; s++) {
        uint32_t k2 = (uint32_t)(s * 16) * 2;
        uint32_t ah[MW][4], al[MW][4];
        #pragma unroll
        for (int m = 0; m < MW; m++) {
            uint32_t abase = sb + (uint32_t)(mbase + m * 16) * SA + k2 + aoff;
            ldsm4(ah[m][0], ah[m][1], ah[m][2], ah[m][3], abase + OFF_AH);
            ldsm4(al[m][0], al[m][1], al[m][2], al[m][3], abase + OFF_AL);
        }
        #pragma unroll
        for (int n = 0; n < NW; n++) {
            uint32_t bh0, bh1, bl0, bl1;
            uint32_t baddr = sb + bside + (uint32_t)(wnb + n * 8) * SA + k2 + boff;
            ldsm4(bh0, bh1, bl0, bl1, baddr);
            #pragma unroll
            for (int m = 0; m < MW; m++) {
                mma16816(acc[m][n], ah[m], bh0, bh1);
                mma16816(acc[m][n], al[m], bh0, bh1);
                mma16816(acc[m][n], ah[m], bl0, bl1);
            }
        }
    }
    __syncthreads();   // smem reads done; reuse front of smem as staging

    // ---- epilogue: fragments -> staging smem -> coalesced gmem ----
    int qr = lane >> 2, qc = lane & 3;
    if (HALF_OUT) {
        uint32_t* st = reinterpret_cast<uint32_t*>(smem);      // [128][65] words
        #pragma unroll
        for (int m = 0; m < MW; m++) {
            int rr = mbase + m * 16 + qr;
            float dv0 = 1.f, dv1 = 1.f;
            if (SCALE) {
                int i0 = row0 + rr;     if (i0 > nrows - 1) i0 = nrows - 1;
                int i1 = row0 + rr + 8; if (i1 > nrows - 1) i1 = nrows - 1;
                dv0 = g_dinv[i0];
                dv1 = g_dinv[i1];
            }
            #pragma unroll
            for (int n = 0; n < NW; n++) {
                int cw = (wnb + n * 8) / 2 + qc;
                __half2 v0 = __floats2half2_rn(acc[m][n][0] * dv0, acc[m][n][1] * dv0);
                __half2 v1 = __floats2half2_rn(acc[m][n][2] * dv1, acc[m][n][3] * dv1);
                st[rr * 65 + cw]       = h2u(v0);
                st[(rr + 8) * 65 + cw] = h2u(v1);
            }
        }
    } else {
        float* st = reinterpret_cast<float*>(smem);            // [128][44] floats
        #pragma unroll
        for (int m = 0; m < MW; m++)
            #pragma unroll
            for (int n = 0; n < NW; n++) {
                int rr = mbase + m * 16 + qr;
                int cb = wnb + n * 8 + 2 * qc;
                st[rr * 44 + cb]           = acc[m][n][0];
                st[rr * 44 + cb + 1]       = acc[m][n][1];
                st[(rr + 8) * 44 + cb]     = acc[m][n][2];
                st[(rr + 8) * 44 + cb + 1] = acc[m][n][3];
            }
    }
    __syncthreads();

    int valid = nrows - row0;
    if (valid > 128) valid = 128;
    if (HALF_OUT) {
        const uint32_t* st = reinterpret_cast<const uint32_t*>(smem);
        uint32_t* g = reinterpret_cast<uint32_t*>(Cv) + (size_t)row0 * (NCOL / 2);
        int nw = valid * (NCOL / 2);
        for (int i = t; i < nw; i += 256) {
            int rr = i / (NCOL / 2), cc = i % (NCOL / 2);
            g[i] = st[rr * 65 + cc];
        }
    } else {
        const float* st = reinterpret_cast<const float*>(smem);
        float* g = reinterpret_cast<float*>(Cv) + (size_t)row0 * NCOL;
        int nw = valid * NCOL;
        for (int i = t; i < nw; i += 256) {
            int rr = i / NCOL, cc = i % NCOL;
            float v = st[rr * 44 + cc];
            if (BIAS) v += bias[cc];
            g[i] = v;
        }
    }
}

// ------------------------- aggregation (warp per node, bucketed) -----------
// SRCSCALE (layer 1): h unscaled ->
//   out[d] = dv*( sum h[s]*dinv[s] + h[d]*dv ) + bias
// !SRCSCALE (layer 2): h pre-scaled by dinv ->
//   out[d] = dv*( sum h'[s] + h'[d] ) + bias
// fp16 in/out; BN stats fused into epilogue.
template <bool SRCSCALE>
__global__ void __launch_bounds__(256)
agg_kernel(const __half* __restrict__ h, const float* __restrict__ bias,
           __half* __restrict__ out, int which) {
    __shared__ float ssum[HH], ssq[HH];
    int t = threadIdx.x;
    if (t < HH) { ssum[t] = 0.f; ssq[t] = 0.f; }
    __syncthreads();

    int gwarp  = (blockIdx.x * blockDim.x + t) >> 5;
    int lane   = t & 31;
    int nwarps = (gridDim.x * blockDim.x) >> 5;
    const uint2* h2v = reinterpret_cast<const uint2*>(h);
    uint2* out2 = reinterpret_cast<uint2*>(out);
    float4 bsv = reinterpret_cast<const float4*>(bias)[lane];

    float bx = 0.f, by = 0.f, bz = 0.f, bw = 0.f;
    float qx = 0.f, qy = 0.f, qz = 0.f, qw = 0.f;

    #define ACCS(rr, cc)                                                       \
        {                                                                      \
            float2 f0 = __half22float2(*reinterpret_cast<__half2*>(&rr.x));    \
            float2 f1 = __half22float2(*reinterpret_cast<__half2*>(&rr.y));    \
            if (SRCSCALE) {                                                    \
                ax = fmaf(f0.x, cc, ax); ay = fmaf(f0.y, cc, ay);              \
                az = fmaf(f1.x, cc, az); aw = fmaf(f1.y, cc, aw);              \
            } else {                                                           \
                ax += f0.x; ay += f0.y; az += f1.x; aw += f1.y;                \
            }                                                                  \
        }

    for (int d = gwarp; d < NN; d += nwarps) {
        int cnt = g_cnt[d];
        if (cnt > SLOTS) cnt = SLOTS;
        const int* cols = g_slot + (size_t)d * SLOTS;
        float dv = g_dinv[d];
        float ax = 0.f, ay = 0.f, az = 0.f, aw = 0.f;

        int e = 0;
        for (; e + 8 <= cnt; e += 8) {
            int s0 = cols[e],     s1 = cols[e + 1];
            int s2 = cols[e + 2], s3 = cols[e + 3];
            int s4 = cols[e + 4], s5 = cols[e + 5];
            int s6 = cols[e + 6], s7 = cols[e + 7];
            float c0 = 0.f, c1 = 0.f, c2 = 0.f, c3 = 0.f;
            float c4 = 0.f, c5 = 0.f, c6 = 0.f, c7 = 0.f;
            if (SRCSCALE) {
                c0 = g_dinv[s0]; c1 = g_dinv[s1]; c2 = g_dinv[s2]; c3 = g_dinv[s3];
                c4 = g_dinv[s4]; c5 = g_dinv[s5]; c6 = g_dinv[s6]; c7 = g_dinv[s7];
            }
            uint2 r0 = h2v[(size_t)s0 * 32 + lane];
            uint2 r1 = h2v[(size_t)s1 * 32 + lane];
            uint2 r2 = h2v[(size_t)s2 * 32 + lane];
            uint2 r3 = h2v[(size_t)s3 * 32 + lane];
            uint2 r4 = h2v[(size_t)s4 * 32 + lane];
            uint2 r5 = h2v[(size_t)s5 * 32 + lane];
            uint2 r6 = h2v[(size_t)s6 * 32 + lane];
            uint2 r7 = h2v[(size_t)s7 * 32 + lane];
            ACCS(r0, c0) ACCS(r1, c1) ACCS(r2, c2) ACCS(r3, c3)
            ACCS(r4, c4) ACCS(r5, c5) ACCS(r6, c6) ACCS(r7, c7)
        }
        for (; e < cnt; e++) {
            int s = cols[e];
            float c = SRCSCALE ? g_dinv[s] : 0.f;
            uint2 rr = h2v[(size_t)s * 32 + lane];
            ACCS(rr, c)
        }

        {   // self loop
            uint2 rr = h2v[(size_t)d * 32 + lane];
            float2 f0 = __half22float2(*reinterpret_cast<__half2*>(&rr.x));
            float2 f1 = __half22float2(*reinterpret_cast<__half2*>(&rr.y));
            if (SRCSCALE) {
                ax = fmaf(f0.x, dv, ax); ay = fmaf(f0.y, dv, ay);
                az = fmaf(f1.x, dv, az); aw = fmaf(f1.y, dv, aw);
            } else {
                ax += f0.x; ay += f0.y; az += f1.x; aw += f1.y;
            }
        }
        ax = fmaf(ax, dv, bsv.x);
        ay = fmaf(ay, dv, bsv.y);
        az = fmaf(az, dv, bsv.z);
        aw = fmaf(aw, dv, bsv.w);

        __half2 p0 = __floats2half2_rn(ax, ay);
        __half2 p1 = __floats2half2_rn(az, aw);
        out2[(size_t)d * 32 + lane] = make_uint2(h2u(p0), h2u(p1));

        bx += ax; by += ay; bz += az; bw += aw;
        qx = fmaf(ax, ax, qx); qy = fmaf(ay, ay, qy);
        qz = fmaf(az, az, qz); qw = fmaf(aw, aw, qw);
    }
    #undef ACCS

    int c0 = 4 * lane;
    atomicAdd(&ssum[c0 + 0], bx); atomicAdd(&ssum[c0 + 1], by);
    atomicAdd(&ssum[c0 + 2], bz); atomicAdd(&ssum[c0 + 3], bw);
    atomicAdd(&ssq[c0 + 0], qx);  atomicAdd(&ssq[c0 + 1], qy);
    atomicAdd(&ssq[c0 + 2], qz);  atomicAdd(&ssq[c0 + 3], qw);
    __syncthreads();
    if (t < HH)      atomicAdd(&g_bnsum[which][t], ssum[t]);
    else             atomicAdd(&g_bnsum[which][t], ssq[t - HH]);
}

// ------------------------- launch ------------------------------------------
extern "C" void kernel_launch(void* const* d_in, const int* in_sizes, int n_in,
                              void* d_out, int out_size) {
    const float* x   = (const float*)d_in[0];
    const int*  esrc = (const int*)d_in[1];
    const int*  edst = (const int*)d_in[2];
    const float* W1  = (const float*)d_in[3];
    const float* b1  = (const float*)d_in[4];
    const float* g1  = (const float*)d_in[5];
    const float* bt1 = (const float*)d_in[6];
    const float* W2  = (const float*)d_in[7];
    const float* b2  = (const float*)d_in[8];
    const float* g2  = (const float*)d_in[9];
    const float* bt2 = (const float*)d_in[10];
    const float* Wr  = (const float*)d_in[11];
    const float* br  = (const float*)d_in[12];
    float* out = (float*)d_out;

    void *pHa, *pHb, *pCnt, *pBn;
    void *w1h, *w1l, *w2h, *w2l, *wrh, *wrl;
    cudaGetSymbolAddress(&pHa, g_h16a);
    cudaGetSymbolAddress(&pHb, g_h16b);
    cudaGetSymbolAddress(&pCnt, g_cnt);
    cudaGetSymbolAddress(&pBn, g_bnsum);
    cudaGetSymbolAddress(&w1h, g_w1hi); cudaGetSymbolAddress(&w1l, g_w1lo);
    cudaGetSymbolAddress(&w2h, g_w2hi); cudaGetSymbolAddress(&w2l, g_w2lo);
    cudaGetSymbolAddress(&wrh, g_wrhi); cudaGetSymbolAddress(&wrl, g_wrlo);

    const int SMEM_H = 2 * 34816 + 2 * 128 * 272;   // 139264
    const int SMEM_R = 2 * 34816 + 2 * OUTC * 272;  //  91392
    cudaFuncSetAttribute(mma_gemm_kernel<HH, false, false, true, false, false>,
                         cudaFuncAttributeMaxDynamicSharedMemorySize, SMEM_H);
    cudaFuncSetAttribute(mma_gemm_kernel<HH, true, false, true, true, true>,
                         cudaFuncAttributeMaxDynamicSharedMemorySize, SMEM_H);
    cudaFuncSetAttribute(mma_gemm_kernel<OUTC, true, true, false, true, false>,
                         cudaFuncAttributeMaxDynamicSharedMemorySize, SMEM_R);

    // side stream + fork/join events for graph-captured overlap
    cudaStream_t s1;
    cudaStreamCreateWithFlags(&s1, cudaStreamNonBlocking);
    cudaEvent_t evRoot, evG1;
    cudaEventCreateWithFlags(&evRoot, cudaEventDisableTiming);
    cudaEventCreateWithFlags(&evG1, cudaEventDisableTiming);

    cudaMemsetAsync(pCnt, 0, NN * sizeof(int));
    cudaMemsetAsync(pBn, 0, sizeof(float) * 2 * 2 * HH);

    // fork: weight prep + layer-1 GEMM (independent of CSR) on side stream
    cudaEventRecord(evRoot, 0);
    cudaStreamWaitEvent(s1, evRoot, 0);
    wprep_all_kernel<<<148, 256, 0, s1>>>(W1, W2, Wr);

    const int GEMM_GRID = (NN + 127) / 128;   // 782
    const int AGG_GRID  = 1184;

    mma_gemm_kernel<HH, false, false, true, false, false><<<GEMM_GRID, 256, SMEM_H, s1>>>(
        x, (const __half*)w1h, (const __half*)w1l, nullptr, nullptr, nullptr, 0,
        pHa, NN);
    cudaEventRecord(evG1, s1);

    // CSR build (direct bucketed) + dinv on main stream, overlapped with gemm1
    fill_direct_kernel<<<512, 256>>>((const int4*)esrc, (const int4*)edst);
    dinv_kernel<<<(NN + 255) / 256, 256>>>();

    // join, then the serial tail
    cudaStreamWaitEvent(0, evG1, 0);
    agg_kernel<true><<<AGG_GRID, 256>>>((const __half*)pHa, b1, (__half*)pHb, 0);

    mma_gemm_kernel<HH, true, false, true, true, true><<<GEMM_GRID, 256, SMEM_H>>>(
        pHb, (const __half*)w2h, (const __half*)w2l, nullptr, g1, bt1, 0,
        pHa, NN);
    agg_kernel<false><<<AGG_GRID, 256>>>((const __half*)pHa, b2, (__half*)pHb, 1);

    mma_gemm_kernel<OUTC, true, true, false, true, false><<<GEMM_GRID, 256, SMEM_R>>>(
        pHb, (const __half*)wrh, (const __half*)wrl, br, g2, bt2, 1,
        out, NN);
}

// round 17
// speedup vs baseline: 1.1239x; 1.1239x over previous
#include <cuda_runtime.h>
#include <cuda_fp16.h>
#include <cstdint>

// ---------------------------------------------------------------------------
// GCN_10591389352000 : 2-layer GCN + BN(train)/ReLU + linear readout
//   N=100000 nodes, E=1600000 edges, IN=H=128, OUT=40
// R16 = R11 revert (bucketed CSR of R12/13 regressed; per-edge dinv gather
//       proved to cost ~25-30us) + isolated deltas:
//   - agg gather batches widened 8 -> 16 (deeper MLP where the bubble was)
//   - g_bnsum memset folded into wprep (one less prefix launch)
//   - everything else identical to the verified 296.8us R11 kernel
// ---------------------------------------------------------------------------

constexpr int NN   = 100000;
constexpr int EE   = 1600000;
constexpr int HH   = 128;
constexpr int OUTC = 40;
constexpr int NB_SCAN = (NN + 1023) / 1024;

// ------------------------- device scratch (static) -------------------------
__device__ __half g_h16a[(size_t)NN * HH];  // 25.6 MB (GEMM out, agg in)
__device__ __half g_h16b[(size_t)NN * HH];  // 25.6 MB (agg out, GEMM in)
__device__ int    g_deg[NN];
__device__ int    g_rowoff[NN + 1];
__device__ int    g_cursor[NN];
__device__ int    g_col[EE];
__device__ float  g_dinv[NN];
__device__ int    g_blocksum[NB_SCAN];
__device__ float  g_bnsum[2][2 * HH];
// weight images: transposed [N][K] fp16, hi/lo split
__device__ __align__(16) __half g_w1hi[HH * HH];
__device__ __align__(16) __half g_w1lo[HH * HH];
__device__ __align__(16) __half g_w2hi[HH * HH];
__device__ __align__(16) __half g_w2lo[HH * HH];
__device__ __align__(16) __half g_wrhi[OUTC * HH];
__device__ __align__(16) __half g_wrlo[OUTC * HH];

// ------------------------- PTX helpers -------------------------------------
__device__ __forceinline__ uint32_t smem_u32(const void* p) {
    uint32_t a;
    asm("{ .reg .u64 t; cvta.to.shared.u64 t, %1; cvt.u32.u64 %0, t; }"
        : "=r"(a) : "l"(p));
    return a;
}
__device__ __forceinline__ void ldsm4(uint32_t& r0, uint32_t& r1, uint32_t& r2,
                                      uint32_t& r3, uint32_t addr) {
    asm volatile("ldmatrix.sync.aligned.m8n8.x4.shared.b16 {%0,%1,%2,%3}, [%4];"
                 : "=r"(r0), "=r"(r1), "=r"(r2), "=r"(r3) : "r"(addr));
}
__device__ __forceinline__ void mma16816(float* c, const uint32_t* a,
                                         uint32_t b0, uint32_t b1) {
    asm volatile("mma.sync.aligned.m16n8k16.row.col.f32.f16.f16.f32 "
                 "{%0,%1,%2,%3}, {%4,%5,%6,%7}, {%8,%9}, {%0,%1,%2,%3};"
                 : "+f"(c[0]), "+f"(c[1]), "+f"(c[2]), "+f"(c[3])
                 : "r"(a[0]), "r"(a[1]), "r"(a[2]), "r"(a[3]), "r"(b0), "r"(b1));
}
__device__ __forceinline__ uint32_t h2u(__half2 v) {
    return *reinterpret_cast<uint32_t*>(&v);
}

// ------------------------- CSR build kernels -------------------------------
__global__ void deg_count_kernel(const int4* __restrict__ dst4) {
    for (int e = blockIdx.x * blockDim.x + threadIdx.x; e < EE / 4;
         e += gridDim.x * blockDim.x) {
        int4 d = dst4[e];
        atomicAdd(&g_deg[d.x], 1);
        atomicAdd(&g_deg[d.y], 1);
        atomicAdd(&g_deg[d.z], 1);
        atomicAdd(&g_deg[d.w], 1);
    }
}

__global__ void scan1_kernel() {
    __shared__ int sh[1024];
    int t = threadIdx.x;
    int i = blockIdx.x * 1024 + t;
    int v = (i < NN) ? g_deg[i] : 0;
    sh[t] = v;
    __syncthreads();
    #pragma unroll
    for (int off = 1; off < 1024; off <<= 1) {
        int add = (t >= off) ? sh[t - off] : 0;
        __syncthreads();
        sh[t] += add;
        __syncthreads();
    }
    if (i < NN) g_rowoff[i] = sh[t] - v;
    if (t == 1023) g_blocksum[blockIdx.x] = sh[1023];
}

__global__ void scan3_kernel() {
    __shared__ int sh[128];
    int t = threadIdx.x;
    if (t < 128) sh[t] = (t < NB_SCAN) ? g_blocksum[t] : 0;
    __syncthreads();
    #pragma unroll
    for (int off = 1; off < 128; off <<= 1) {
        int add = (t < 128 && t >= off) ? sh[t - off] : 0;
        __syncthreads();
        if (t < 128) sh[t] += add;
        __syncthreads();
    }
    int i = blockIdx.x * blockDim.x + t;
    if (i < NN) {
        int b = i >> 10;
        int boff = sh[b] - g_blocksum[b];
        int r = g_rowoff[i] + boff;
        g_rowoff[i] = r;
        g_cursor[i] = r;
        g_dinv[i] = rsqrtf((float)g_deg[i] + 1.0f);
        if (i == 0) g_rowoff[NN] = EE;
    }
}

__global__ void fill_kernel(const int4* __restrict__ src4,
                            const int4* __restrict__ dst4) {
    for (int e = blockIdx.x * blockDim.x + threadIdx.x; e < EE / 4;
         e += gridDim.x * blockDim.x) {
        int4 d = dst4[e];
        int4 s = src4[e];
        g_col[atomicAdd(&g_cursor[d.x], 1)] = s.x;
        g_col[atomicAdd(&g_cursor[d.y], 1)] = s.y;
        g_col[atomicAdd(&g_cursor[d.z], 1)] = s.z;
        g_col[atomicAdd(&g_cursor[d.w], 1)] = s.w;
    }
}

// ------------------------- weight prep (+ bnsum zeroing) --------------------
__global__ void wprep_all_kernel(const float* __restrict__ W1,
                                 const float* __restrict__ W2,
                                 const float* __restrict__ Wr) {
    if (blockIdx.x == 0) {
        float* bs = &g_bnsum[0][0];
        for (int i = threadIdx.x; i < 2 * 2 * HH; i += blockDim.x) bs[i] = 0.f;
    }
    constexpr int T1 = HH * HH, T2 = 2 * HH * HH, T3 = 2 * HH * HH + OUTC * HH;
    for (int i = blockIdx.x * blockDim.x + threadIdx.x; i < T3;
         i += gridDim.x * blockDim.x) {
        const float* W;
        __half *hi, *lo;
        int Ncols, idx;
        if (i < T1)      { W = W1; hi = g_w1hi; lo = g_w1lo; Ncols = HH;   idx = i; }
        else if (i < T2) { W = W2; hi = g_w2hi; lo = g_w2lo; Ncols = HH;   idx = i - T1; }
        else             { W = Wr; hi = g_wrhi; lo = g_wrlo; Ncols = OUTC; idx = i - T2; }
        int n = idx / HH, k = idx % HH;
        float w = W[k * Ncols + n];
        __half h = __float2half_rn(w);
        hi[n * HH + k] = h;
        lo[n * HH + k] = __float2half_rn(w - __half2float(h));
    }
}

// ------------------------- tensor-core GEMM --------------------------------
// C[nrows, NCOL] = act(A[nrows,128]) @ W[128, NCOL] (+ bias), CTA tile M=128.
// FUSED: BN affine (per-CTA from g_bnsum/gamma/beta) + ReLU on A load.
// SCALE: multiply output row r by g_dinv[r] before fp16 store (for agg).
template <int NCOL, bool FUSED, bool BIAS, bool HALF_OUT, bool HALF_IN, bool SCALE>
__global__ void __launch_bounds__(256, 1)
mma_gemm_kernel(const void* __restrict__ Av, const __half* __restrict__ Bhi,
                const __half* __restrict__ Blo, const float* __restrict__ bias,
                const float* __restrict__ gamma, const float* __restrict__ beta,
                int which, void* __restrict__ Cv, int nrows) {
    constexpr int SA     = 272;                 // bytes per smem row
    constexpr int OFF_AH = 0;
    constexpr int OFF_AL = 128 * SA;            // 34816
    constexpr int OFF_BH = 2 * 128 * SA;        // 69632
    constexpr int OFF_BL = OFF_BH + NCOL * SA;
    constexpr int MW = (NCOL == 128) ? 2 : 1;
    constexpr int NW = (NCOL == 128) ? 8 : 5;

    extern __shared__ char smem[];
    __shared__ float s_sc[HH], s_sh[HH];
    uint32_t sb = smem_u32(smem);
    int t = threadIdx.x, wid = t >> 5, lane = t & 31;
    int row0 = blockIdx.x * 128;

    if (FUSED) {
        if (t < HH) {
            float mean = g_bnsum[which][t] * (1.0f / NN);
            float var  = g_bnsum[which][HH + t] * (1.0f / NN) - mean * mean;
            float sc   = gamma[t] * rsqrtf(var + 1e-5f);
            s_sc[t] = sc;
            s_sh[t] = fmaf(-mean, sc, beta[t]);
        }
        __syncthreads();
    }

    int mbase, wnb;
    if (NCOL == 128) { mbase = (wid & 3) * 32; wnb = (wid >> 2) * 64; }
    else             { mbase = wid * 16;       wnb = 0; }

    // ---- B copy: gmem image [n][k] fp16 -> padded smem rows ----
    {
        const uint4* shp = reinterpret_cast<const uint4*>(Bhi);
        const uint4* slp = reinterpret_cast<const uint4*>(Blo);
        uint4* dh = reinterpret_cast<uint4*>(smem + OFF_BH);
        uint4* dl = reinterpret_cast<uint4*>(smem + OFF_BL);
        for (int i = t; i < NCOL * 16; i += 256) {
            int n = i >> 4, j = i & 15;
            dh[n * 17 + j] = shp[i];
            dl[n * 17 + j] = slp[i];
        }
    }
    // ---- A load + (affine/relu) + hi/lo split -> padded smem ----
    {
        int r = t >> 1, kh = (t & 1) * 64;
        int grow = row0 + r;
        if (grow > nrows - 1) grow = nrows - 1;
        #pragma unroll
        for (int u = 0; u < 8; u++) {
            int k = kh + u * 8;
            float v[8];
            if (HALF_IN) {
                const uint4* Ar = reinterpret_cast<const uint4*>(
                    (const __half*)Av + (size_t)grow * HH + k);
                uint4 raw = Ar[0];
                float2 f0 = __half22float2(*reinterpret_cast<__half2*>(&raw.x));
                float2 f1 = __half22float2(*reinterpret_cast<__half2*>(&raw.y));
                float2 f2 = __half22float2(*reinterpret_cast<__half2*>(&raw.z));
                float2 f3 = __half22float2(*reinterpret_cast<__half2*>(&raw.w));
                v[0] = f0.x; v[1] = f0.y; v[2] = f1.x; v[3] = f1.y;
                v[4] = f2.x; v[5] = f2.y; v[6] = f3.x; v[7] = f3.y;
            } else {
                const float4* Ar = reinterpret_cast<const float4*>(
                    (const float*)Av + (size_t)grow * HH + k);
                float4 a = Ar[0], b = Ar[1];
                v[0] = a.x; v[1] = a.y; v[2] = a.z; v[3] = a.w;
                v[4] = b.x; v[5] = b.y; v[6] = b.z; v[7] = b.w;
            }
            if (FUSED) {
                #pragma unroll
                for (int j = 0; j < 8; j++)
                    v[j] = fmaxf(fmaf(v[j], s_sc[k + j], s_sh[k + j]), 0.f);
            }
            __half hv[8];
            uint4 hh, ll;
            #pragma unroll
            for (int j = 0; j < 8; j++) hv[j] = __float2half_rn(v[j]);
            hh.x = h2u(__halves2half2(hv[0], hv[1]));
            hh.y = h2u(__halves2half2(hv[2], hv[3]));
            hh.z = h2u(__halves2half2(hv[4], hv[5]));
            hh.w = h2u(__halves2half2(hv[6], hv[7]));
            ll.x = h2u(__halves2half2(__float2half_rn(v[0] - __half2float(hv[0])),
                                      __float2half_rn(v[1] - __half2float(hv[1]))));
            ll.y = h2u(__halves2half2(__float2half_rn(v[2] - __half2float(hv[2])),
                                      __float2half_rn(v[3] - __half2float(hv[3]))));
            ll.z = h2u(__halves2half2(__float2half_rn(v[4] - __half2float(hv[4])),
                                      __float2half_rn(v[5] - __half2float(hv[5]))));
            ll.w = h2u(__halves2half2(__float2half_rn(v[6] - __half2float(hv[6])),
                                      __float2half_rn(v[7] - __half2float(hv[7]))));
            uint32_t off = (uint32_t)r * SA + (uint32_t)k * 2;
            *reinterpret_cast<uint4*>(smem + OFF_AH + off) = hh;
            *reinterpret_cast<uint4*>(smem + OFF_AL + off) = ll;
        }
    }
    __syncthreads();

    // ---- fragment address offsets (per lane) ----
    uint32_t aoff = (uint32_t)((lane & 7) + ((lane >> 3) & 1) * 8) * SA
                  + (uint32_t)(((lane >> 4) & 1) * 8) * 2;
    uint32_t bside = (lane >= 16) ? (uint32_t)OFF_BL : (uint32_t)OFF_BH;
    uint32_t boff  = (uint32_t)(lane & 7) * SA + (uint32_t)(((lane >> 3) & 1) * 8) * 2;

    float acc[MW][NW][4];
    #pragma unroll
    for (int m = 0; m < MW; m++)
        #pragma unroll
        for (int n = 0; n < NW; n++)
            #pragma unroll
            for (int c = 0; c < 4; c++) acc[m][n][c] = 0.f;

    #pragma unroll
    for (int s = 0; s < 8; s++) {
        uint32_t k2 = (uint32_t)(s * 16) * 2;
        uint32_t ah[MW][4], al[MW][4];
        #pragma unroll
        for (int m = 0; m < MW; m++) {
            uint32_t abase = sb + (uint32_t)(mbase + m * 16) * SA + k2 + aoff;
            ldsm4(ah[m][0], ah[m][1], ah[m][2], ah[m][3], abase + OFF_AH);
            ldsm4(al[m][0], al[m][1], al[m][2], al[m][3], abase + OFF_AL);
        }
        #pragma unroll
        for (int n = 0; n < NW; n++) {
            uint32_t bh0, bh1, bl0, bl1;
            uint32_t baddr = sb + bside + (uint32_t)(wnb + n * 8) * SA + k2 + boff;
            ldsm4(bh0, bh1, bl0, bl1, baddr);
            #pragma unroll
            for (int m = 0; m < MW; m++) {
                mma16816(acc[m][n], ah[m], bh0, bh1);
                mma16816(acc[m][n], al[m], bh0, bh1);
                mma16816(acc[m][n], ah[m], bl0, bl1);
            }
        }
    }
    __syncthreads();   // smem reads done; reuse front of smem as staging

    // ---- epilogue: fragments -> staging smem -> coalesced gmem ----
    int qr = lane >> 2, qc = lane & 3;
    if (HALF_OUT) {
        uint32_t* st = reinterpret_cast<uint32_t*>(smem);      // [128][65] words
        #pragma unroll
        for (int m = 0; m < MW; m++) {
            int rr = mbase + m * 16 + qr;
            float dv0 = 1.f, dv1 = 1.f;
            if (SCALE) {
                int i0 = row0 + rr;     if (i0 > nrows - 1) i0 = nrows - 1;
                int i1 = row0 + rr + 8; if (i1 > nrows - 1) i1 = nrows - 1;
                dv0 = g_dinv[i0];
                dv1 = g_dinv[i1];
            }
            #pragma unroll
            for (int n = 0; n < NW; n++) {
                int cw = (wnb + n * 8) / 2 + qc;
                __half2 v0 = __floats2half2_rn(acc[m][n][0] * dv0, acc[m][n][1] * dv0);
                __half2 v1 = __floats2half2_rn(acc[m][n][2] * dv1, acc[m][n][3] * dv1);
                st[rr * 65 + cw]       = h2u(v0);
                st[(rr + 8) * 65 + cw] = h2u(v1);
            }
        }
    } else {
        float* st = reinterpret_cast<float*>(smem);            // [128][44] floats
        #pragma unroll
        for (int m = 0; m < MW; m++)
            #pragma unroll
            for (int n = 0; n < NW; n++) {
                int rr = mbase + m * 16 + qr;
                int cb = wnb + n * 8 + 2 * qc;
                st[rr * 44 + cb]           = acc[m][n][0];
                st[rr * 44 + cb + 1]       = acc[m][n][1];
                st[(rr + 8) * 44 + cb]     = acc[m][n][2];
                st[(rr + 8) * 44 + cb + 1] = acc[m][n][3];
            }
    }
    __syncthreads();

    int valid = nrows - row0;
    if (valid > 128) valid = 128;
    if (HALF_OUT) {
        const uint32_t* st = reinterpret_cast<const uint32_t*>(smem);
        uint32_t* g = reinterpret_cast<uint32_t*>(Cv) + (size_t)row0 * (NCOL / 2);
        int nw = valid * (NCOL / 2);
        for (int i = t; i < nw; i += 256) {
            int rr = i / (NCOL / 2), cc = i % (NCOL / 2);
            g[i] = st[rr * 65 + cc];
        }
    } else {
        const float* st = reinterpret_cast<const float*>(smem);
        float* g = reinterpret_cast<float*>(Cv) + (size_t)row0 * NCOL;
        int nw = valid * NCOL;
        for (int i = t; i < nw; i += 256) {
            int rr = i / NCOL, cc = i % NCOL;
            float v = st[rr * 44 + cc];
            if (BIAS) v += bias[cc];
            g[i] = v;
        }
    }
}

// ------------------------- aggregation (warp per node) ---------------------
// h' is pre-scaled by dinv (GEMM epilogue). Per node:
//   out[d] = dv * ( sum_{e: dst=d} h'[src_e] + h'[d] ) + bias
// fp16 in, fp16 out; BN stats from fp32 values fused into epilogue.
// Gather batches of 16 (then 4, then 1) for deep MLP.
__global__ void __launch_bounds__(256)
agg_kernel(const __half* __restrict__ h, const float* __restrict__ bias,
           __half* __restrict__ out, int which) {
    __shared__ float ssum[HH], ssq[HH];
    int t = threadIdx.x;
    if (t < HH) { ssum[t] = 0.f; ssq[t] = 0.f; }
    __syncthreads();

    int gwarp  = (blockIdx.x * blockDim.x + t) >> 5;
    int lane   = t & 31;
    int nwarps = (gridDim.x * blockDim.x) >> 5;
    const uint2* h2v = reinterpret_cast<const uint2*>(h);
    uint2* out2 = reinterpret_cast<uint2*>(out);
    float4 bsv = reinterpret_cast<const float4*>(bias)[lane];

    float bx = 0.f, by = 0.f, bz = 0.f, bw = 0.f;
    float qx = 0.f, qy = 0.f, qz = 0.f, qw = 0.f;

    #define ACC4(rr)                                                           \
        {                                                                      \
            float2 f0 = __half22float2(*reinterpret_cast<__half2*>(&rr.x));    \
            float2 f1 = __half22float2(*reinterpret_cast<__half2*>(&rr.y));    \
            ax += f0.x; ay += f0.y; az += f1.x; aw += f1.y;                    \
        }

    for (int d = gwarp; d < NN; d += nwarps) {
        int e   = g_rowoff[d];
        int end = g_rowoff[d + 1];
        float dv = g_dinv[d];
        float ax = 0.f, ay = 0.f, az = 0.f, aw = 0.f;

        // 16-wide batches: 16 independent 256B gathers in flight
        for (; e + 16 <= end; e += 16) {
            int s[16];
            #pragma unroll
            for (int j = 0; j < 16; j++) s[j] = g_col[e + j];
            uint2 r[16];
            #pragma unroll
            for (int j = 0; j < 16; j++) r[j] = h2v[(size_t)s[j] * 32 + lane];
            #pragma unroll
            for (int j = 0; j < 16; j++) { ACC4(r[j]) }
        }
        for (; e + 4 <= end; e += 4) {
            int s[4];
            #pragma unroll
            for (int j = 0; j < 4; j++) s[j] = g_col[e + j];
            uint2 r[4];
            #pragma unroll
            for (int j = 0; j < 4; j++) r[j] = h2v[(size_t)s[j] * 32 + lane];
            #pragma unroll
            for (int j = 0; j < 4; j++) { ACC4(r[j]) }
        }
        for (; e < end; e++) {
            int s = g_col[e];
            uint2 rr = h2v[(size_t)s * 32 + lane];
            ACC4(rr)
        }

        {   // self loop: h'[d] already carries dinv[d]
            uint2 rr = h2v[(size_t)d * 32 + lane];
            ACC4(rr)
        }
        ax = fmaf(ax, dv, bsv.x);
        ay = fmaf(ay, dv, bsv.y);
        az = fmaf(az, dv, bsv.z);
        aw = fmaf(aw, dv, bsv.w);

        __half2 p0 = __floats2half2_rn(ax, ay);
        __half2 p1 = __floats2half2_rn(az, aw);
        out2[(size_t)d * 32 + lane] = make_uint2(h2u(p0), h2u(p1));

        bx += ax; by += ay; bz += az; bw += aw;
        qx = fmaf(ax, ax, qx); qy = fmaf(ay, ay, qy);
        qz = fmaf(az, az, qz); qw = fmaf(aw, aw, qw);
    }
    #undef ACC4

    int c0 = 4 * lane;
    atomicAdd(&ssum[c0 + 0], bx); atomicAdd(&ssum[c0 + 1], by);
    atomicAdd(&ssum[c0 + 2], bz); atomicAdd(&ssum[c0 + 3], bw);
    atomicAdd(&ssq[c0 + 0], qx);  atomicAdd(&ssq[c0 + 1], qy);
    atomicAdd(&ssq[c0 + 2], qz);  atomicAdd(&ssq[c0 + 3], qw);
    __syncthreads();
    if (t < HH)      atomicAdd(&g_bnsum[which][t], ssum[t]);
    else             atomicAdd(&g_bnsum[which][t], ssq[t - HH]);
}

// ------------------------- launch ------------------------------------------
extern "C" void kernel_launch(void* const* d_in, const int* in_sizes, int n_in,
                              void* d_out, int out_size) {
    const float* x   = (const float*)d_in[0];
    const int*  esrc = (const int*)d_in[1];
    const int*  edst = (const int*)d_in[2];
    const float* W1  = (const float*)d_in[3];
    const float* b1  = (const float*)d_in[4];
    const float* g1  = (const float*)d_in[5];
    const float* bt1 = (const float*)d_in[6];
    const float* W2  = (const float*)d_in[7];
    const float* b2  = (const float*)d_in[8];
    const float* g2  = (const float*)d_in[9];
    const float* bt2 = (const float*)d_in[10];
    const float* Wr  = (const float*)d_in[11];
    const float* br  = (const float*)d_in[12];
    float* out = (float*)d_out;

    void *pHa, *pHb, *pDeg;
    void *w1h, *w1l, *w2h, *w2l, *wrh, *wrl;
    cudaGetSymbolAddress(&pHa, g_h16a);
    cudaGetSymbolAddress(&pHb, g_h16b);
    cudaGetSymbolAddress(&pDeg, g_deg);
    cudaGetSymbolAddress(&w1h, g_w1hi); cudaGetSymbolAddress(&w1l, g_w1lo);
    cudaGetSymbolAddress(&w2h, g_w2hi); cudaGetSymbolAddress(&w2l, g_w2lo);
    cudaGetSymbolAddress(&wrh, g_wrhi); cudaGetSymbolAddress(&wrl, g_wrlo);

    const int SMEM_H = 2 * 34816 + 2 * 128 * 272;   // 139264
    const int SMEM_R = 2 * 34816 + 2 * OUTC * 272;  //  91392
    cudaFuncSetAttribute(mma_gemm_kernel<HH, false, false, true, false, true>,
                         cudaFuncAttributeMaxDynamicSharedMemorySize, SMEM_H);
    cudaFuncSetAttribute(mma_gemm_kernel<HH, true, false, true, true, true>,
                         cudaFuncAttributeMaxDynamicSharedMemorySize, SMEM_H);
    cudaFuncSetAttribute(mma_gemm_kernel<OUTC, true, true, false, true, false>,
                         cudaFuncAttributeMaxDynamicSharedMemorySize, SMEM_R);

    // side stream + fork/join events for graph-captured overlap
    cudaStream_t s1;
    cudaStreamCreateWithFlags(&s1, cudaStreamNonBlocking);
    cudaEvent_t evRoot, evScan, evG1;
    cudaEventCreateWithFlags(&evRoot, cudaEventDisableTiming);
    cudaEventCreateWithFlags(&evScan, cudaEventDisableTiming);
    cudaEventCreateWithFlags(&evG1, cudaEventDisableTiming);

    cudaMemsetAsync(pDeg, 0, NN * sizeof(int));

    // fork side stream off the main (capture) stream
    cudaEventRecord(evRoot, 0);
    cudaStreamWaitEvent(s1, evRoot, 0);
    wprep_all_kernel<<<148, 256, 0, s1>>>(W1, W2, Wr);

    // CSR build on main stream
    deg_count_kernel<<<512, 256>>>((const int4*)edst);
    scan1_kernel<<<NB_SCAN, 1024>>>();
    scan3_kernel<<<(NN + 255) / 256, 256>>>();
    cudaEventRecord(evScan, 0);       // dinv ready

    const int GEMM_GRID = (NN + 127) / 128;   // 782
    const int AGG_GRID  = 1184;

    // Layer-1 GEMM on side stream (needs x, W1 image, dinv) || fill on main
    cudaStreamWaitEvent(s1, evScan, 0);
    mma_gemm_kernel<HH, false, false, true, false, true><<<GEMM_GRID, 256, SMEM_H, s1>>>(
        x, (const __half*)w1h, (const __half*)w1l, nullptr, nullptr, nullptr, 0,
        pHa, NN);
    cudaEventRecord(evG1, s1);

    fill_kernel<<<512, 256>>>((const int4*)esrc, (const int4*)edst);

    // join, then the serial tail
    cudaStreamWaitEvent(0, evG1, 0);
    agg_kernel<<<AGG_GRID, 256>>>((const __half*)pHa, b1, (__half*)pHb, 0);

    mma_gemm_kernel<HH, true, false, true, true, true><<<GEMM_GRID, 256, SMEM_H>>>(
        pHb, (const __half*)w2h, (const __half*)w2l, nullptr, g1, bt1, 0,
        pHa, NN);
    agg_kernel<<<AGG_GRID, 256>>>((const __half*)pHa, b2, (__half*)pHb, 1);

    mma_gemm_kernel<OUTC, true, true, false, true, false><<<GEMM_GRID, 256, SMEM_R>>>(
        pHb, (const __half*)wrh, (const __half*)wrl, br, g2, bt2, 1,
        out, NN);
}